// round 5
// baseline (speedup 1.0000x reference)
#include <cuda_runtime.h>
#include <cuda_bf16.h>

#define B_  256
#define T_  2048
#define BT  (B_ * T_)
#define NBLK 152

__device__ float2 g_w[BT];           // (wu, wd) states [t][b]
__device__ float  g_params[BT * 8];  // row-major [r][8]
__device__ uint2  g_W1p[32 * 32];
__device__ uint2  g_W2p[16 * 8 * 32];
__device__ uint2  g_W3p[4 * 32];

__device__ __forceinline__ float tanhA(float x) {
    float r; asm("tanh.approx.f32 %0, %1;" : "=f"(r) : "f"(x)); return r;
}
__device__ __forceinline__ float heav(float x10) {   // h given 10*x
    return fmaf(0.5f, tanhA(x10), 0.5f);
}
__device__ __forceinline__ float sigm1(float x) {
    return fmaf(0.5f, tanhA(0.5f * x), 0.5f);
}
__device__ __forceinline__ unsigned int packbf(float lo, float hi) {
    unsigned int r;
    asm("cvt.rn.bf16x2.f32 %0, %1, %2;" : "=r"(r) : "f"(hi), "f"(lo));
    return r;
}
__device__ __forceinline__ void mma16816(float& c0, float& c1, float& c2, float& c3,
                                         unsigned int a0, unsigned int a1,
                                         unsigned int a2, unsigned int a3,
                                         unsigned int b0, unsigned int b1) {
    asm volatile(
        "mma.sync.aligned.m16n8k16.row.col.f32.bf16.bf16.f32 "
        "{%0,%1,%2,%3},{%4,%5,%6,%7},{%8,%9},{%0,%1,%2,%3};\n"
        : "+f"(c0), "+f"(c1), "+f"(c2), "+f"(c3)
        : "r"(a0), "r"(a1), "r"(a2), "r"(a3), "r"(b0), "r"(b1));
}

// ---- prep: pack weights into mma B fragments (tiny, 1 block) -----------------
__global__ void prep_kernel(const float* __restrict__ w1,
                            const float* __restrict__ w2,
                            const float* __restrict__ w3) {
    int tid = threadIdx.x;
    for (int i = tid; i < 32 * 32; i += 256) {           // W1 (15x256), k-pad to 16
        int lane = i & 31, nt = i >> 5;
        int g = lane >> 2, tig = lane & 3;
        int n = nt * 8 + g;
        float e0 = w1[(2 * tig) * 256 + n];
        float e1 = w1[(2 * tig + 1) * 256 + n];
        int k2 = 2 * tig + 8, k3 = 2 * tig + 9;
        float e2 = (k2 < 15) ? w1[k2 * 256 + n] : 0.0f;
        float e3 = (k3 < 15) ? w1[k3 * 256 + n] : 0.0f;
        g_W1p[i] = make_uint2(packbf(e0, e1), packbf(e2, e3));
    }
    for (int i = tid; i < 16 * 8 * 32; i += 256) {       // W2 (256x64)
        int lane = i & 31;
        int nt = (i >> 5) & 7;
        int kc = i >> 8;
        int g = lane >> 2, tig = lane & 3;
        int n = nt * 8 + g;
        int k0 = kc * 16 + 2 * tig;
        g_W2p[i] = make_uint2(packbf(w2[k0 * 64 + n], w2[(k0 + 1) * 64 + n]),
                              packbf(w2[(k0 + 8) * 64 + n], w2[(k0 + 9) * 64 + n]));
    }
    for (int i = tid; i < 4 * 32; i += 256) {            // W3 (64x8)
        int lane = i & 31;
        int kc = i >> 5;
        int g = lane >> 2, tig = lane & 3;
        int k0 = kc * 16 + 2 * tig;
        g_W3p[i] = make_uint2(packbf(w3[k0 * 8 + g], w3[(k0 + 1) * 8 + g]),
                              packbf(w3[(k0 + 8) * 8 + g], w3[(k0 + 9) * 8 + g]));
    }
}

// ================ scan stage macros (3-stage software pipeline) ================
// B2(i-2): wd update, consumes yB,hyB,sd2B
#define SCAN_B2()                                                          \
  { float t3  = tanhA(fmaf(10.0f, yB, m10wd));                             \
    float et3 = hyB * fmaf(t3, 0.5f * (wd - yB), 0.5f * (wd + yB));        \
    wd += sd2B - et3;                                                      \
    m10wd = -10.0f * wd; }

// B1(i-1): wl update + et2, consumes zA,rpA,hrpA,ppvA; produces yB,hyB,sd2B
#define SCAN_B1()                                                          \
  { float tw  = tanhA(fmaf(10.0f, rpA, m10wl));                            \
    float et2 = hrpA * fmaf(tw, 0.5f * (wl - rpA), 0.5f * (wl + rpA));     \
    float sd2 = ppvA + zA - et2;                                           \
    wl += sd2;                                                             \
    m10wl = -10.0f * wl;                                                   \
    float y  = rpA - et2;                                                  \
    float ty = tanhA(10.0f * y);                                           \
    yB = y; hyB = fmaf(0.5f, ty, 0.5f); sd2B = sd2; }

// A(i): wu update + rp chain; produces zA,rpA,hrpA,ppvA
#define SCAN_A(PET, PV)                                                    \
  { float ppv = (PV) - (PET);                                              \
    float d1  = (PET) - wu;                                                \
    float t1  = tanhA(10.0f * d1);                                         \
    float z   = fmaf(t1, 0.5f * d1, 0.5f * d1);                            \
    float wuN = wu + ppv + z;                                              \
    float tz  = tanhA(10.0f * z);                                          \
    float rp  = fmaf(tz, 0.5f * z, 0.5f * z);                              \
    float trp = tanhA(10.0f * rp);                                         \
    zA = z; rpA = rp; hrpA = fmaf(0.5f, trp, 0.5f); ppvA = ppv;            \
    wuS2 = wuS1; wuS1 = wuN; wu = wuN; }

#define SCAN_BODY(I, SLOT)                                                 \
  { float4 qq = q##SLOT;                                                   \
    if ((I) + 6 < T_) q##SLOT = row4[base + ((I) + 6) * 5];                \
    SCAN_B2();                                                             \
    g_w[((I) - 2) * B_ + b] = make_float2(wuS2, wd);                       \
    SCAN_B1();                                                             \
    SCAN_A(qq.x, qq.z); }

// ---- fused persistent kernel: 1 block/SM -------------------------------------
__global__ void __launch_bounds__(256)
main_kernel(const float* __restrict__ in,
            const float* __restrict__ b1v,
            const float* __restrict__ b2v,
            const float* __restrict__ b3v) {
    __shared__ uint2 sW1[32 * 32];
    __shared__ uint2 sW2[16 * 8 * 32];
    __shared__ uint2 sW3[4 * 32];
    __shared__ float sB1[256];
    __shared__ float sB2[64];
    __shared__ float sB3[8];

    if (blockIdx.x < 2) {
        // ===================== scan: 1 thread/basin, 1 warp/SMSP ================
        if (threadIdx.x >= 128) return;
        int b = blockIdx.x * 128 + threadIdx.x;       // 0..255
        const float4* __restrict__ row4 = reinterpret_cast<const float4*>(in);
        int base = b * (T_ * 5);                      // row t -> base + t*5 (float4)

        float wu = 0.0f, wl = 0.0f, wd = 0.0f;
        float m10wl = 0.0f, m10wd = 0.0f;
        float wuS1 = 0.0f, wuS2 = 0.0f;
        float zA = 0.0f, rpA = 0.0f, hrpA = 0.0f, ppvA = 0.0f;
        float yB = 0.0f, hyB = 0.0f, sd2B = 0.0f;

        float4 q0 = row4[base + 0 * 5];
        float4 q1 = row4[base + 1 * 5];
        float4 q2 = row4[base + 2 * 5];
        float4 q3 = row4[base + 3 * 5];
        float4 q4 = row4[base + 4 * 5];
        float4 q5 = row4[base + 5 * 5];

        // prologue: body 0 (A only), body 1 (B1 + A)
        { float4 qq = q0; q0 = row4[base + 6 * 5]; SCAN_A(qq.x, qq.z); }
        { float4 qq = q1; q1 = row4[base + 7 * 5]; SCAN_B1(); SCAN_A(qq.x, qq.z); }

        // main: bodies 2..2047  (341 groups of 6)
        for (int i = 2; i < T_; i += 6) {
            SCAN_BODY(i + 0, 2);
            SCAN_BODY(i + 1, 3);
            SCAN_BODY(i + 2, 4);
            SCAN_BODY(i + 3, 5);
            SCAN_BODY(i + 4, 0);
            SCAN_BODY(i + 5, 1);
        }

        // epilogue: body 2048 (B2 + store + B1), body 2049 (B2 + store)
        SCAN_B2();
        g_w[2046 * B_ + b] = make_float2(wuS2, wd);
        SCAN_B1();
        SCAN_B2();
        g_w[2047 * B_ + b] = make_float2(wuS1, wd);
        return;
    }

    // ===================== persistent MLP ==================================
    for (int i = threadIdx.x; i < 32 * 32; i += 256)     sW1[i] = g_W1p[i];
    for (int i = threadIdx.x; i < 16 * 8 * 32; i += 256) sW2[i] = g_W2p[i];
    for (int i = threadIdx.x; i < 4 * 32; i += 256)      sW3[i] = g_W3p[i];
    if (threadIdx.x < 256) sB1[threadIdx.x] = b1v[threadIdx.x];
    if (threadIdx.x < 64)  sB2[threadIdx.x] = b2v[threadIdx.x];
    if (threadIdx.x < 8)   sB3[threadIdx.x] = b3v[threadIdx.x];
    __syncthreads();

    int warp = threadIdx.x >> 5;
    int lane = threadIdx.x & 31;
    int g    = lane >> 2, tig = lane & 3;
    int wg   = (blockIdx.x - 2) * 8 + warp;

    for (int tile = wg; tile < 32768; tile += (NBLK - 2) * 8) {
        int r0 = tile * 16 + g;
        int r1 = r0 + 8;

        unsigned int A0, A1, A2, A3;
        {
            const float* q0p = in + r0 * 20 + 5;
            const float* q1p = in + r1 * 20 + 5;
            float x0 = q0p[2 * tig],     x1 = q0p[2 * tig + 1];
            float y0 = q1p[2 * tig],     y1 = q1p[2 * tig + 1];
            float x2 = q0p[2 * tig + 8];
            float y2 = q1p[2 * tig + 8];
            float x3 = (tig < 3) ? q0p[2 * tig + 9] : 0.0f;
            float y3 = (tig < 3) ? q1p[2 * tig + 9] : 0.0f;
            A0 = packbf(x0, x1); A1 = packbf(y0, y1);
            A2 = packbf(x2, x3); A3 = packbf(y2, y3);
        }

        // stage 1: h1 = tanh(attrs @ W1 + b1)
        unsigned int h1a[16][4];
#pragma unroll
        for (int nt = 0; nt < 32; ++nt) {
            uint2 w = sW1[nt * 32 + lane];
            float c0 = 0.f, c1 = 0.f, c2 = 0.f, c3 = 0.f;
            mma16816(c0, c1, c2, c3, A0, A1, A2, A3, w.x, w.y);
            int   n0  = nt * 8 + 2 * tig;
            float bb0 = sB1[n0], bb1 = sB1[n0 + 1];
            c0 = tanhA(c0 + bb0); c1 = tanhA(c1 + bb1);
            c2 = tanhA(c2 + bb0); c3 = tanhA(c3 + bb1);
            h1a[nt >> 1][(nt & 1) * 2 + 0] = packbf(c0, c1);
            h1a[nt >> 1][(nt & 1) * 2 + 1] = packbf(c2, c3);
        }

        // stage 2: h2 = tanh(h1 @ W2 + b2)
        float acc[8][4];
#pragma unroll
        for (int nt = 0; nt < 8; ++nt) { acc[nt][0] = acc[nt][1] = acc[nt][2] = acc[nt][3] = 0.0f; }
#pragma unroll
        for (int kc = 0; kc < 16; ++kc) {
#pragma unroll
            for (int nt = 0; nt < 8; ++nt) {
                uint2 w = sW2[(kc * 8 + nt) * 32 + lane];
                mma16816(acc[nt][0], acc[nt][1], acc[nt][2], acc[nt][3],
                         h1a[kc][0], h1a[kc][1], h1a[kc][2], h1a[kc][3], w.x, w.y);
            }
        }
        unsigned int h2a[4][4];
#pragma unroll
        for (int nt = 0; nt < 8; ++nt) {
            int   n0  = nt * 8 + 2 * tig;
            float bb0 = sB2[n0], bb1 = sB2[n0 + 1];
            float c0 = tanhA(acc[nt][0] + bb0), c1 = tanhA(acc[nt][1] + bb1);
            float c2 = tanhA(acc[nt][2] + bb0), c3 = tanhA(acc[nt][3] + bb1);
            h2a[nt >> 1][(nt & 1) * 2 + 0] = packbf(c0, c1);
            h2a[nt >> 1][(nt & 1) * 2 + 1] = packbf(c2, c3);
        }

        // stage 3: params = sigmoid(h2 @ W3 + b3)
        float p0 = 0.f, p1 = 0.f, p2 = 0.f, p3 = 0.f;
#pragma unroll
        for (int kc = 0; kc < 4; ++kc) {
            uint2 w = sW3[kc * 32 + lane];
            mma16816(p0, p1, p2, p3, h2a[kc][0], h2a[kc][1], h2a[kc][2], h2a[kc][3], w.x, w.y);
        }
        int   n0  = 2 * tig;
        float bb0 = sB3[n0], bb1 = sB3[n0 + 1];
        p0 = sigm1(p0 + bb0);
        p1 = sigm1(p1 + bb1);
        p2 = sigm1(p2 + bb0);
        p3 = sigm1(p3 + bb1);
        *reinterpret_cast<float2*>(&g_params[r0 * 8 + n0]) = make_float2(p0, p1);
        *reinterpret_cast<float2*>(&g_params[r1 * 8 + n0]) = make_float2(p2, p3);
    }
}

// ---- final pointwise: runoff + partition (reference's swapped args!) ----------
__global__ void final_kernel(const float* __restrict__ in, float* __restrict__ out) {
    int r = blockIdx.x * 256 + threadIdx.x;     // r = b*T + t
    int b = r >> 11, t = r & 2047;
    float2 w = g_w[t * B_ + b];
    float wu = w.x, wd = w.y;
    float p  = in[r * 20 + 2];
    float4 q0 = *reinterpret_cast<const float4*>(&g_params[r * 8]);
    float4 q1 = *reinterpret_cast<const float4*>(&g_params[r * 8 + 4]);
    float wum = q0.x, wlm = q0.y, wdm = q0.z, bb = q0.w;
    float cc  = q1.x, k1 = q1.y, k2 = q1.z, k3 = q1.w;

    // reference calls _runoff(wu, wd, wl, p, wum, wdm, wlm, b, c)
    float wum_s = wum * 19.9f + 0.1f;
    float wlm_s = wdm * 30.0f + 60.0f;   // inner wlm <- outer wdm
    float wdm_s = wlm * 60.0f + 60.0f;   // inner wdm <- outer wlm
    float c_s   = cc * 0.19f + 0.01f;
    float b_s   = bb * 0.3f + 0.1f;
    float wt    = wum_s + wlm_s + wdm_s;
    float iwt   = __frcp_rn(wt);
    float u = wu * iwt;                  // inner wu
    float v = wd * iwt;                  // inner wl <- outer wd
    float s = c_s * u * u + b_s * v * v;
    float d = p - s;
    float runoff = heav(10.0f * d) * d;

    float k1s = k1 * 0.69f + 0.01f;
    float k2s = k2 * 0.69f + 0.01f;
    float k3s = k3 * 0.89f + 0.01f;
    float sr  = k1s * runoff;
    float itf = k2s * (runoff - sr);
    float bf  = k3s * (runoff - sr - itf);
    out[r] = sr + 0.5f * itf + 0.25f * bf;
}

extern "C" void kernel_launch(void* const* d_in, const int* in_sizes, int n_in,
                              void* d_out, int out_size) {
    const float* in  = (const float*)d_in[0];
    const float* w1  = (const float*)d_in[1];
    const float* b1  = (const float*)d_in[2];
    const float* w2  = (const float*)d_in[3];
    const float* b2  = (const float*)d_in[4];
    const float* w3  = (const float*)d_in[5];
    const float* b3  = (const float*)d_in[6];
    float* out = (float*)d_out;
    prep_kernel<<<1, 256>>>(w1, w2, w3);
    main_kernel<<<NBLK, 256>>>(in, b1, b2, b3);
    final_kernel<<<2048, 256>>>(in, out);
}

// round 6
// speedup vs baseline: 1.4733x; 1.4733x over previous
#include <cuda_runtime.h>
#include <cuda_bf16.h>

#define B_  256
#define T_  2048
#define BT  (B_ * T_)
#define NBLK 152

__device__ float2 g_pp[BT];          // (pet, p) transposed [t][b]
__device__ float2 g_w[BT];           // (wu, wd) states [t][b]
__device__ float  g_params[BT * 8];  // row-major [r][8]
__device__ uint2  g_W1p[32 * 32];
__device__ uint2  g_W2p[16 * 8 * 32];
__device__ uint2  g_W3p[4 * 32];

__device__ __forceinline__ float tanhA(float x) {
    float r; asm("tanh.approx.f32 %0, %1;" : "=f"(r) : "f"(x)); return r;
}
__device__ __forceinline__ float heav(float x10) {   // h given 10*x
    return fmaf(0.5f, tanhA(x10), 0.5f);
}
__device__ __forceinline__ float sigm1(float x) {
    return fmaf(0.5f, tanhA(0.5f * x), 0.5f);
}
__device__ __forceinline__ unsigned int packbf(float lo, float hi) {
    unsigned int r;
    asm("cvt.rn.bf16x2.f32 %0, %1, %2;" : "=r"(r) : "f"(hi), "f"(lo));
    return r;
}
__device__ __forceinline__ void mma16816(float& c0, float& c1, float& c2, float& c3,
                                         unsigned int a0, unsigned int a1,
                                         unsigned int a2, unsigned int a3,
                                         unsigned int b0, unsigned int b1) {
    asm volatile(
        "mma.sync.aligned.m16n8k16.row.col.f32.bf16.bf16.f32 "
        "{%0,%1,%2,%3},{%4,%5,%6,%7},{%8,%9},{%0,%1,%2,%3};\n"
        : "+f"(c0), "+f"(c1), "+f"(c2), "+f"(c3)
        : "r"(a0), "r"(a1), "r"(a2), "r"(a3), "r"(b0), "r"(b1));
}

// ---- prep: transpose (pet,p) into g_pp + pack weights -------------------------
__global__ void prep_kernel(const float* __restrict__ in,
                            const float* __restrict__ w1,
                            const float* __restrict__ w2,
                            const float* __restrict__ w3) {
    int bid = blockIdx.x;
    if (bid < 2048) {
        int r = bid * 256 + threadIdx.x;       // r = b*T + t
        int b = r >> 11;
        int t = r & 2047;
        float4 q = reinterpret_cast<const float4*>(in)[r * 5];   // row cols 0..3
        g_pp[t * B_ + b] = make_float2(q.x, q.z);                // (pet, p)
        return;
    }
    int tid = threadIdx.x;
    for (int i = tid; i < 32 * 32; i += 256) {           // W1 (15x256), k-pad to 16
        int lane = i & 31, nt = i >> 5;
        int g = lane >> 2, tig = lane & 3;
        int n = nt * 8 + g;
        float e0 = w1[(2 * tig) * 256 + n];
        float e1 = w1[(2 * tig + 1) * 256 + n];
        int k2 = 2 * tig + 8, k3 = 2 * tig + 9;
        float e2 = (k2 < 15) ? w1[k2 * 256 + n] : 0.0f;
        float e3 = (k3 < 15) ? w1[k3 * 256 + n] : 0.0f;
        g_W1p[i] = make_uint2(packbf(e0, e1), packbf(e2, e3));
    }
    for (int i = tid; i < 16 * 8 * 32; i += 256) {       // W2 (256x64)
        int lane = i & 31;
        int nt = (i >> 5) & 7;
        int kc = i >> 8;
        int g = lane >> 2, tig = lane & 3;
        int n = nt * 8 + g;
        int k0 = kc * 16 + 2 * tig;
        g_W2p[i] = make_uint2(packbf(w2[k0 * 64 + n], w2[(k0 + 1) * 64 + n]),
                              packbf(w2[(k0 + 8) * 64 + n], w2[(k0 + 9) * 64 + n]));
    }
    for (int i = tid; i < 4 * 32; i += 256) {            // W3 (64x8)
        int lane = i & 31;
        int kc = i >> 5;
        int g = lane >> 2, tig = lane & 3;
        int k0 = kc * 16 + 2 * tig;
        g_W3p[i] = make_uint2(packbf(w3[k0 * 8 + g], w3[(k0 + 1) * 8 + g]),
                              packbf(w3[(k0 + 8) * 8 + g], w3[(k0 + 9) * 8 + g]));
    }
}

// ================ scan stage macros (3-stage software pipeline) ================
#define SCAN_B2()                                                          \
  { float t3  = tanhA(fmaf(10.0f, yB, m10wd));                             \
    float et3 = hyB * fmaf(t3, 0.5f * (wd - yB), 0.5f * (wd + yB));        \
    wd += sd2B - et3;                                                      \
    m10wd = -10.0f * wd; }

#define SCAN_B1()                                                          \
  { float tw  = tanhA(fmaf(10.0f, rpA, m10wl));                            \
    float et2 = hrpA * fmaf(tw, 0.5f * (wl - rpA), 0.5f * (wl + rpA));     \
    float sd2 = ppvA + zA - et2;                                           \
    wl += sd2;                                                             \
    m10wl = -10.0f * wl;                                                   \
    float y  = rpA - et2;                                                  \
    float ty = tanhA(10.0f * y);                                           \
    yB = y; hyB = fmaf(0.5f, ty, 0.5f); sd2B = sd2; }

#define SCAN_A(PET, PV)                                                    \
  { float ppv = (PV) - (PET);                                              \
    float d1  = (PET) - wu;                                                \
    float t1  = tanhA(10.0f * d1);                                         \
    float z   = fmaf(t1, 0.5f * d1, 0.5f * d1);                            \
    float wuN = wu + ppv + z;                                              \
    float tz  = tanhA(10.0f * z);                                          \
    float rp  = fmaf(tz, 0.5f * z, 0.5f * z);                              \
    float trp = tanhA(10.0f * rp);                                         \
    zA = z; rpA = rp; hrpA = fmaf(0.5f, trp, 0.5f); ppvA = ppv;            \
    wuS2 = wuS1; wuS1 = wuN; wu = wuN; }

#define SCAN_BODY(I, SLOT)                                                 \
  { float2 qq = q##SLOT;                                                   \
    if ((I) + 6 < T_) q##SLOT = g_pp[((I) + 6) * B_ + b];                  \
    SCAN_B2();                                                             \
    g_w[((I) - 2) * B_ + b] = make_float2(wuS2, wd);                       \
    SCAN_B1();                                                             \
    SCAN_A(qq.x, qq.y); }

// ---- fused persistent kernel: 1 block/SM -------------------------------------
__global__ void __launch_bounds__(256)
main_kernel(const float* __restrict__ in,
            const float* __restrict__ b1v,
            const float* __restrict__ b2v,
            const float* __restrict__ b3v) {
    __shared__ uint2 sW1[32 * 32];
    __shared__ uint2 sW2[16 * 8 * 32];
    __shared__ uint2 sW3[4 * 32];
    __shared__ float sB1[256];
    __shared__ float sB2[64];
    __shared__ float sB3[8];

    if (blockIdx.x < 2) {
        // ===================== scan: 1 thread/basin, 1 warp/SMSP ================
        if (threadIdx.x >= 128) return;
        int b = blockIdx.x * 128 + threadIdx.x;       // 0..255

        float wu = 0.0f, wl = 0.0f, wd = 0.0f;
        float m10wl = 0.0f, m10wd = 0.0f;
        float wuS1 = 0.0f, wuS2 = 0.0f;
        float zA = 0.0f, rpA = 0.0f, hrpA = 0.0f, ppvA = 0.0f;
        float yB = 0.0f, hyB = 0.0f, sd2B = 0.0f;

        float2 q0 = g_pp[0 * B_ + b];
        float2 q1 = g_pp[1 * B_ + b];
        float2 q2 = g_pp[2 * B_ + b];
        float2 q3 = g_pp[3 * B_ + b];
        float2 q4 = g_pp[4 * B_ + b];
        float2 q5 = g_pp[5 * B_ + b];

        // prologue: body 0 (A only), body 1 (B1 + A)
        { float2 qq = q0; q0 = g_pp[6 * B_ + b]; SCAN_A(qq.x, qq.y); }
        { float2 qq = q1; q1 = g_pp[7 * B_ + b]; SCAN_B1(); SCAN_A(qq.x, qq.y); }

        // main: bodies 2..2047  (341 groups of 6)
        for (int i = 2; i < T_; i += 6) {
            SCAN_BODY(i + 0, 2);
            SCAN_BODY(i + 1, 3);
            SCAN_BODY(i + 2, 4);
            SCAN_BODY(i + 3, 5);
            SCAN_BODY(i + 4, 0);
            SCAN_BODY(i + 5, 1);
        }

        // epilogue
        SCAN_B2();
        g_w[2046 * B_ + b] = make_float2(wuS2, wd);
        SCAN_B1();
        SCAN_B2();
        g_w[2047 * B_ + b] = make_float2(wuS1, wd);
        return;
    }

    // ===================== persistent MLP ==================================
    for (int i = threadIdx.x; i < 32 * 32; i += 256)     sW1[i] = g_W1p[i];
    for (int i = threadIdx.x; i < 16 * 8 * 32; i += 256) sW2[i] = g_W2p[i];
    for (int i = threadIdx.x; i < 4 * 32; i += 256)      sW3[i] = g_W3p[i];
    if (threadIdx.x < 256) sB1[threadIdx.x] = b1v[threadIdx.x];
    if (threadIdx.x < 64)  sB2[threadIdx.x] = b2v[threadIdx.x];
    if (threadIdx.x < 8)   sB3[threadIdx.x] = b3v[threadIdx.x];
    __syncthreads();

    int warp = threadIdx.x >> 5;
    int lane = threadIdx.x & 31;
    int g    = lane >> 2, tig = lane & 3;
    int wg   = (blockIdx.x - 2) * 8 + warp;

    for (int tile = wg; tile < 32768; tile += (NBLK - 2) * 8) {
        int r0 = tile * 16 + g;
        int r1 = r0 + 8;

        unsigned int A0, A1, A2, A3;
        {
            const float* q0p = in + r0 * 20 + 5;
            const float* q1p = in + r1 * 20 + 5;
            float x0 = q0p[2 * tig],     x1 = q0p[2 * tig + 1];
            float y0 = q1p[2 * tig],     y1 = q1p[2 * tig + 1];
            float x2 = q0p[2 * tig + 8];
            float y2 = q1p[2 * tig + 8];
            float x3 = (tig < 3) ? q0p[2 * tig + 9] : 0.0f;
            float y3 = (tig < 3) ? q1p[2 * tig + 9] : 0.0f;
            A0 = packbf(x0, x1); A1 = packbf(y0, y1);
            A2 = packbf(x2, x3); A3 = packbf(y2, y3);
        }

        // stage 1: h1 = tanh(attrs @ W1 + b1)
        unsigned int h1a[16][4];
#pragma unroll
        for (int nt = 0; nt < 32; ++nt) {
            uint2 w = sW1[nt * 32 + lane];
            float c0 = 0.f, c1 = 0.f, c2 = 0.f, c3 = 0.f;
            mma16816(c0, c1, c2, c3, A0, A1, A2, A3, w.x, w.y);
            int   n0  = nt * 8 + 2 * tig;
            float bb0 = sB1[n0], bb1 = sB1[n0 + 1];
            c0 = tanhA(c0 + bb0); c1 = tanhA(c1 + bb1);
            c2 = tanhA(c2 + bb0); c3 = tanhA(c3 + bb1);
            h1a[nt >> 1][(nt & 1) * 2 + 0] = packbf(c0, c1);
            h1a[nt >> 1][(nt & 1) * 2 + 1] = packbf(c2, c3);
        }

        // stage 2: h2 = tanh(h1 @ W2 + b2)
        float acc[8][4];
#pragma unroll
        for (int nt = 0; nt < 8; ++nt) { acc[nt][0] = acc[nt][1] = acc[nt][2] = acc[nt][3] = 0.0f; }
#pragma unroll
        for (int kc = 0; kc < 16; ++kc) {
#pragma unroll
            for (int nt = 0; nt < 8; ++nt) {
                uint2 w = sW2[(kc * 8 + nt) * 32 + lane];
                mma16816(acc[nt][0], acc[nt][1], acc[nt][2], acc[nt][3],
                         h1a[kc][0], h1a[kc][1], h1a[kc][2], h1a[kc][3], w.x, w.y);
            }
        }
        unsigned int h2a[4][4];
#pragma unroll
        for (int nt = 0; nt < 8; ++nt) {
            int   n0  = nt * 8 + 2 * tig;
            float bb0 = sB2[n0], bb1 = sB2[n0 + 1];
            float c0 = tanhA(acc[nt][0] + bb0), c1 = tanhA(acc[nt][1] + bb1);
            float c2 = tanhA(acc[nt][2] + bb0), c3 = tanhA(acc[nt][3] + bb1);
            h2a[nt >> 1][(nt & 1) * 2 + 0] = packbf(c0, c1);
            h2a[nt >> 1][(nt & 1) * 2 + 1] = packbf(c2, c3);
        }

        // stage 3: params = sigmoid(h2 @ W3 + b3)
        float p0 = 0.f, p1 = 0.f, p2 = 0.f, p3 = 0.f;
#pragma unroll
        for (int kc = 0; kc < 4; ++kc) {
            uint2 w = sW3[kc * 32 + lane];
            mma16816(p0, p1, p2, p3, h2a[kc][0], h2a[kc][1], h2a[kc][2], h2a[kc][3], w.x, w.y);
        }
        int   n0  = 2 * tig;
        float bb0 = sB3[n0], bb1 = sB3[n0 + 1];
        p0 = sigm1(p0 + bb0);
        p1 = sigm1(p1 + bb1);
        p2 = sigm1(p2 + bb0);
        p3 = sigm1(p3 + bb1);
        *reinterpret_cast<float2*>(&g_params[r0 * 8 + n0]) = make_float2(p0, p1);
        *reinterpret_cast<float2*>(&g_params[r1 * 8 + n0]) = make_float2(p2, p3);
    }
}

// ---- final pointwise: runoff + partition (reference's swapped args!) ----------
__global__ void final_kernel(const float* __restrict__ in, float* __restrict__ out) {
    int r = blockIdx.x * 256 + threadIdx.x;     // r = b*T + t
    int b = r >> 11, t = r & 2047;
    float2 w = g_w[t * B_ + b];
    float wu = w.x, wd = w.y;
    float p  = in[r * 20 + 2];
    float4 q0 = *reinterpret_cast<const float4*>(&g_params[r * 8]);
    float4 q1 = *reinterpret_cast<const float4*>(&g_params[r * 8 + 4]);
    float wum = q0.x, wlm = q0.y, wdm = q0.z, bb = q0.w;
    float cc  = q1.x, k1 = q1.y, k2 = q1.z, k3 = q1.w;

    // reference calls _runoff(wu, wd, wl, p, wum, wdm, wlm, b, c)
    float wum_s = wum * 19.9f + 0.1f;
    float wlm_s = wdm * 30.0f + 60.0f;   // inner wlm <- outer wdm
    float wdm_s = wlm * 60.0f + 60.0f;   // inner wdm <- outer wlm
    float c_s   = cc * 0.19f + 0.01f;
    float b_s   = bb * 0.3f + 0.1f;
    float wt    = wum_s + wlm_s + wdm_s;
    float iwt   = __frcp_rn(wt);
    float u = wu * iwt;                  // inner wu
    float v = wd * iwt;                  // inner wl <- outer wd
    float s = c_s * u * u + b_s * v * v;
    float d = p - s;
    float runoff = heav(10.0f * d) * d;

    float k1s = k1 * 0.69f + 0.01f;
    float k2s = k2 * 0.69f + 0.01f;
    float k3s = k3 * 0.89f + 0.01f;
    float sr  = k1s * runoff;
    float itf = k2s * (runoff - sr);
    float bf  = k3s * (runoff - sr - itf);
    out[r] = sr + 0.5f * itf + 0.25f * bf;
}

extern "C" void kernel_launch(void* const* d_in, const int* in_sizes, int n_in,
                              void* d_out, int out_size) {
    const float* in  = (const float*)d_in[0];
    const float* w1  = (const float*)d_in[1];
    const float* b1  = (const float*)d_in[2];
    const float* w2  = (const float*)d_in[3];
    const float* b2  = (const float*)d_in[4];
    const float* w3  = (const float*)d_in[5];
    const float* b3  = (const float*)d_in[6];
    float* out = (float*)d_out;
    prep_kernel<<<2049, 256>>>(in, w1, w2, w3);
    main_kernel<<<NBLK, 256>>>(in, b1, b2, b3);
    final_kernel<<<2048, 256>>>(in, out);
}

// round 7
// speedup vs baseline: 1.5777x; 1.0709x over previous
#include <cuda_runtime.h>
#include <cuda_bf16.h>

#define B_  256
#define T_  2048
#define BT  (B_ * T_)
#define NBLK 152

__device__ float4 g_pp[BT + 8 * B_];   // (10*pet, 0.5*pet, p-pet, 0) [t][b], padded
__device__ float4 g_w[(T_ / 2) * B_];  // (wu0,wd0,wu1,wd1) per t-pair [t/2][b]
__device__ float  g_params[BT * 8];    // row-major [r][8]
__device__ uint2  g_W1p[32 * 32];
__device__ uint2  g_W2p[16 * 8 * 32];
__device__ uint2  g_W3p[4 * 32];

__device__ __forceinline__ float tanhA(float x) {
    float r; asm("tanh.approx.f32 %0, %1;" : "=f"(r) : "f"(x)); return r;
}
__device__ __forceinline__ float heav(float x10) {   // h given 10*x
    return fmaf(0.5f, tanhA(x10), 0.5f);
}
__device__ __forceinline__ float sigm1(float x) {
    return fmaf(0.5f, tanhA(0.5f * x), 0.5f);
}
__device__ __forceinline__ unsigned int packbf(float lo, float hi) {
    unsigned int r;
    asm("cvt.rn.bf16x2.f32 %0, %1, %2;" : "=r"(r) : "f"(hi), "f"(lo));
    return r;
}
__device__ __forceinline__ void mma16816(float& c0, float& c1, float& c2, float& c3,
                                         unsigned int a0, unsigned int a1,
                                         unsigned int a2, unsigned int a3,
                                         unsigned int b0, unsigned int b1) {
    asm volatile(
        "mma.sync.aligned.m16n8k16.row.col.f32.bf16.bf16.f32 "
        "{%0,%1,%2,%3},{%4,%5,%6,%7},{%8,%9},{%0,%1,%2,%3};\n"
        : "+f"(c0), "+f"(c1), "+f"(c2), "+f"(c3)
        : "r"(a0), "r"(a1), "r"(a2), "r"(a3), "r"(b0), "r"(b1));
}

// ---- prep: stage scan inputs + pack weights -----------------------------------
__global__ void prep_kernel(const float* __restrict__ in,
                            const float* __restrict__ w1,
                            const float* __restrict__ w2,
                            const float* __restrict__ w3) {
    int bid = blockIdx.x;
    if (bid < 2048) {
        int r = bid * 256 + threadIdx.x;       // r = b*T + t
        int b = r >> 11;
        int t = r & 2047;
        float4 q = reinterpret_cast<const float4*>(in)[r * 5];   // cols 0..3
        g_pp[t * B_ + b] = make_float4(10.0f * q.x, 0.5f * q.x, q.z - q.x, 0.0f);
        return;
    }
    int tid = threadIdx.x;
    for (int i = tid; i < 32 * 32; i += 256) {           // W1 (15x256), k-pad to 16
        int lane = i & 31, nt = i >> 5;
        int g = lane >> 2, tig = lane & 3;
        int n = nt * 8 + g;
        float e0 = w1[(2 * tig) * 256 + n];
        float e1 = w1[(2 * tig + 1) * 256 + n];
        int k2 = 2 * tig + 8, k3 = 2 * tig + 9;
        float e2 = (k2 < 15) ? w1[k2 * 256 + n] : 0.0f;
        float e3 = (k3 < 15) ? w1[k3 * 256 + n] : 0.0f;
        g_W1p[i] = make_uint2(packbf(e0, e1), packbf(e2, e3));
    }
    for (int i = tid; i < 16 * 8 * 32; i += 256) {       // W2 (256x64)
        int lane = i & 31;
        int nt = (i >> 5) & 7;
        int kc = i >> 8;
        int g = lane >> 2, tig = lane & 3;
        int n = nt * 8 + g;
        int k0 = kc * 16 + 2 * tig;
        g_W2p[i] = make_uint2(packbf(w2[k0 * 64 + n], w2[(k0 + 1) * 64 + n]),
                              packbf(w2[(k0 + 8) * 64 + n], w2[(k0 + 9) * 64 + n]));
    }
    for (int i = tid; i < 4 * 32; i += 256) {            // W3 (64x8)
        int lane = i & 31;
        int kc = i >> 5;
        int g = lane >> 2, tig = lane & 3;
        int k0 = kc * 16 + 2 * tig;
        g_W3p[i] = make_uint2(packbf(w3[k0 * 8 + g], w3[(k0 + 1) * 8 + g]),
                              packbf(w3[(k0 + 8) * 8 + g], w3[(k0 + 9) * 8 + g]));
    }
}

// ================ scan stage macros (3-stage software pipeline) ================
// chains: wu->wu, wl->wl, wd->wd each = fma(4) + tanh(16) + fma(4) + fma(4) = 28cy
#define SCAN_B2()                                                          \
  { float t3     = tanhA(fmaf(-10.0f, wd, y10B));                          \
    float inner2 = fmaf(t3, wd - yB, wd + yB);                             \
    float wdps   = wd + sd2B;                                              \
    wd = fmaf(-vB, inner2, wdps); }

#define SCAN_B1()                                                          \
  { float tw    = tanhA(fmaf(-10.0f, wl, rp10A));                          \
    float inner = fmaf(tw, wl - rpA, wl + rpA);                            \
    float wlpp  = wl + ppvzA;                                              \
    float et2   = uA * inner;                                              \
    wl = fmaf(-uA, inner, wlpp);                                           \
    float y   = rpA - et2;                                                 \
    float y10 = 10.0f * y;                                                 \
    float ty  = tanhA(y10);                                                \
    yB = y; y10B = y10; vB = fmaf(0.25f, ty, 0.25f); sd2B = ppvzA - et2; }

#define SCAN_A(QQ)                                                         \
  { float t1  = tanhA(fmaf(-10.0f, wu, (QQ).x));                           \
    float hd1 = fmaf(-0.5f, wu, (QQ).y);                                   \
    float z   = fmaf(t1, hd1, hd1);                                        \
    float wupp = wu + (QQ).z;                                              \
    wuS3 = wuS2; wuS2 = wuS1; wuS1 = wupp + z; wu = wuS1;                  \
    float tz  = tanhA(10.0f * z);                                          \
    float hz  = 0.5f * z;                                                  \
    float rp  = fmaf(tz, hz, hz);                                          \
    float rp10 = 10.0f * rp;                                               \
    float trp = tanhA(rp10);                                               \
    uA = fmaf(0.25f, trp, 0.25f);                                          \
    rpA = rp; rp10A = rp10; ppvzA = (QQ).z + z; }

#define SCAN_BODY_NS(I, SLOT)                                              \
  { float4 qq = q##SLOT;                                                   \
    q##SLOT = pp[((I) + 6) * B_];                                          \
    SCAN_B2();                                                             \
    SCAN_B1();                                                             \
    SCAN_A(qq); }

#define SCAN_BODY_ST(I, SLOT)                                              \
  { float4 qq = q##SLOT;                                                   \
    q##SLOT = pp[((I) + 6) * B_];                                          \
    float wdP = wd;                                                        \
    SCAN_B2();                                                             \
    wp[(((I) - 2) >> 1) * B_] = make_float4(wuS3, wdP, wuS2, wd);          \
    SCAN_B1();                                                             \
    SCAN_A(qq); }

// ---- fused persistent kernel: 1 block/SM -------------------------------------
__global__ void __launch_bounds__(256)
main_kernel(const float* __restrict__ in,
            const float* __restrict__ b1v,
            const float* __restrict__ b2v,
            const float* __restrict__ b3v) {
    __shared__ uint2 sW1[32 * 32];
    __shared__ uint2 sW2[16 * 8 * 32];
    __shared__ uint2 sW3[4 * 32];
    __shared__ float sB1[256];
    __shared__ float sB2[64];
    __shared__ float sB3[8];

    if (blockIdx.x < 2) {
        // ===================== scan: 1 thread/basin, 1 warp/SMSP ================
        if (threadIdx.x >= 128) return;
        int b = blockIdx.x * 128 + threadIdx.x;       // 0..255
        const float4* __restrict__ pp = g_pp + b;
        float4* __restrict__ wp = g_w + b;

        float wu = 0.0f, wl = 0.0f, wd = 0.0f;
        float wuS1 = 0.0f, wuS2 = 0.0f, wuS3 = 0.0f;
        float rpA = 0.0f, rp10A = 0.0f, uA = 0.25f, ppvzA = 0.0f;
        float yB = 0.0f, y10B = 0.0f, vB = 0.25f, sd2B = 0.0f;

        float4 q0 = pp[0 * B_];
        float4 q1 = pp[1 * B_];
        float4 q2 = pp[2 * B_];
        float4 q3 = pp[3 * B_];
        float4 q4 = pp[4 * B_];
        float4 q5 = pp[5 * B_];

        // prologue: body 0 (A), body 1 (B1 + A)
        { float4 qq = q0; q0 = pp[6 * B_]; SCAN_A(qq); }
        { float4 qq = q1; q1 = pp[7 * B_]; SCAN_B1(); SCAN_A(qq); }

        // main: bodies 2..2047  (341 groups of 6; store at odd (I-2))
        for (int i = 2; i < T_; i += 6) {
            SCAN_BODY_NS(i + 0, 2);
            SCAN_BODY_ST(i + 1, 3);
            SCAN_BODY_NS(i + 2, 4);
            SCAN_BODY_ST(i + 3, 5);
            SCAN_BODY_NS(i + 4, 0);
            SCAN_BODY_ST(i + 5, 1);
        }

        // epilogue: steps 2046, 2047
        SCAN_B2();                       // wd[2046]
        float wd2046 = wd;
        SCAN_B1();                       // produce step-2047 carries
        SCAN_B2();                       // wd[2047]
        wp[1023 * B_] = make_float4(wuS2, wd2046, wuS1, wd);
        return;
    }

    // ===================== persistent MLP ==================================
    for (int i = threadIdx.x; i < 32 * 32; i += 256)     sW1[i] = g_W1p[i];
    for (int i = threadIdx.x; i < 16 * 8 * 32; i += 256) sW2[i] = g_W2p[i];
    for (int i = threadIdx.x; i < 4 * 32; i += 256)      sW3[i] = g_W3p[i];
    if (threadIdx.x < 256) sB1[threadIdx.x] = b1v[threadIdx.x];
    if (threadIdx.x < 64)  sB2[threadIdx.x] = b2v[threadIdx.x];
    if (threadIdx.x < 8)   sB3[threadIdx.x] = b3v[threadIdx.x];
    __syncthreads();

    int warp = threadIdx.x >> 5;
    int lane = threadIdx.x & 31;
    int g    = lane >> 2, tig = lane & 3;
    int wg   = (blockIdx.x - 2) * 8 + warp;

    for (int tile = wg; tile < 32768; tile += (NBLK - 2) * 8) {
        int r0 = tile * 16 + g;
        int r1 = r0 + 8;

        unsigned int A0, A1, A2, A3;
        {
            const float* q0p = in + r0 * 20 + 5;
            const float* q1p = in + r1 * 20 + 5;
            float x0 = q0p[2 * tig],     x1 = q0p[2 * tig + 1];
            float y0 = q1p[2 * tig],     y1 = q1p[2 * tig + 1];
            float x2 = q0p[2 * tig + 8];
            float y2 = q1p[2 * tig + 8];
            float x3 = (tig < 3) ? q0p[2 * tig + 9] : 0.0f;
            float y3 = (tig < 3) ? q1p[2 * tig + 9] : 0.0f;
            A0 = packbf(x0, x1); A1 = packbf(y0, y1);
            A2 = packbf(x2, x3); A3 = packbf(y2, y3);
        }

        // stage 1: h1 = tanh(attrs @ W1 + b1)
        unsigned int h1a[16][4];
#pragma unroll
        for (int nt = 0; nt < 32; ++nt) {
            uint2 w = sW1[nt * 32 + lane];
            float c0 = 0.f, c1 = 0.f, c2 = 0.f, c3 = 0.f;
            mma16816(c0, c1, c2, c3, A0, A1, A2, A3, w.x, w.y);
            int   n0  = nt * 8 + 2 * tig;
            float bb0 = sB1[n0], bb1 = sB1[n0 + 1];
            c0 = tanhA(c0 + bb0); c1 = tanhA(c1 + bb1);
            c2 = tanhA(c2 + bb0); c3 = tanhA(c3 + bb1);
            h1a[nt >> 1][(nt & 1) * 2 + 0] = packbf(c0, c1);
            h1a[nt >> 1][(nt & 1) * 2 + 1] = packbf(c2, c3);
        }

        // stage 2: h2 = tanh(h1 @ W2 + b2)
        float acc[8][4];
#pragma unroll
        for (int nt = 0; nt < 8; ++nt) { acc[nt][0] = acc[nt][1] = acc[nt][2] = acc[nt][3] = 0.0f; }
#pragma unroll
        for (int kc = 0; kc < 16; ++kc) {
#pragma unroll
            for (int nt = 0; nt < 8; ++nt) {
                uint2 w = sW2[(kc * 8 + nt) * 32 + lane];
                mma16816(acc[nt][0], acc[nt][1], acc[nt][2], acc[nt][3],
                         h1a[kc][0], h1a[kc][1], h1a[kc][2], h1a[kc][3], w.x, w.y);
            }
        }
        unsigned int h2a[4][4];
#pragma unroll
        for (int nt = 0; nt < 8; ++nt) {
            int   n0  = nt * 8 + 2 * tig;
            float bb0 = sB2[n0], bb1 = sB2[n0 + 1];
            float c0 = tanhA(acc[nt][0] + bb0), c1 = tanhA(acc[nt][1] + bb1);
            float c2 = tanhA(acc[nt][2] + bb0), c3 = tanhA(acc[nt][3] + bb1);
            h2a[nt >> 1][(nt & 1) * 2 + 0] = packbf(c0, c1);
            h2a[nt >> 1][(nt & 1) * 2 + 1] = packbf(c2, c3);
        }

        // stage 3: params = sigmoid(h2 @ W3 + b3)
        float p0 = 0.f, p1 = 0.f, p2 = 0.f, p3 = 0.f;
#pragma unroll
        for (int kc = 0; kc < 4; ++kc) {
            uint2 w = sW3[kc * 32 + lane];
            mma16816(p0, p1, p2, p3, h2a[kc][0], h2a[kc][1], h2a[kc][2], h2a[kc][3], w.x, w.y);
        }
        int   n0  = 2 * tig;
        float bb0 = sB3[n0], bb1 = sB3[n0 + 1];
        p0 = sigm1(p0 + bb0);
        p1 = sigm1(p1 + bb1);
        p2 = sigm1(p2 + bb0);
        p3 = sigm1(p3 + bb1);
        *reinterpret_cast<float2*>(&g_params[r0 * 8 + n0]) = make_float2(p0, p1);
        *reinterpret_cast<float2*>(&g_params[r1 * 8 + n0]) = make_float2(p2, p3);
    }
}

// ---- final pointwise: runoff + partition (reference's swapped args!) ----------
__global__ void final_kernel(const float* __restrict__ in, float* __restrict__ out) {
    int r = blockIdx.x * 256 + threadIdx.x;     // r = b*T + t
    int b = r >> 11, t = r & 2047;
    float4 wv = g_w[(t >> 1) * B_ + b];
    float wu = (t & 1) ? wv.z : wv.x;
    float wd = (t & 1) ? wv.w : wv.y;
    float p  = in[r * 20 + 2];
    float4 q0 = *reinterpret_cast<const float4*>(&g_params[r * 8]);
    float4 q1 = *reinterpret_cast<const float4*>(&g_params[r * 8 + 4]);
    float wum = q0.x, wlm = q0.y, wdm = q0.z, bb = q0.w;
    float cc  = q1.x, k1 = q1.y, k2 = q1.z, k3 = q1.w;

    // reference calls _runoff(wu, wd, wl, p, wum, wdm, wlm, b, c)
    float wum_s = wum * 19.9f + 0.1f;
    float wlm_s = wdm * 30.0f + 60.0f;   // inner wlm <- outer wdm
    float wdm_s = wlm * 60.0f + 60.0f;   // inner wdm <- outer wlm
    float c_s   = cc * 0.19f + 0.01f;
    float b_s   = bb * 0.3f + 0.1f;
    float wt    = wum_s + wlm_s + wdm_s;
    float iwt   = __frcp_rn(wt);
    float u = wu * iwt;                  // inner wu
    float v = wd * iwt;                  // inner wl <- outer wd
    float s = c_s * u * u + b_s * v * v;
    float d = p - s;
    float runoff = heav(10.0f * d) * d;

    float k1s = k1 * 0.69f + 0.01f;
    float k2s = k2 * 0.69f + 0.01f;
    float k3s = k3 * 0.89f + 0.01f;
    float sr  = k1s * runoff;
    float itf = k2s * (runoff - sr);
    float bf  = k3s * (runoff - sr - itf);
    out[r] = sr + 0.5f * itf + 0.25f * bf;
}

extern "C" void kernel_launch(void* const* d_in, const int* in_sizes, int n_in,
                              void* d_out, int out_size) {
    const float* in  = (const float*)d_in[0];
    const float* w1  = (const float*)d_in[1];
    const float* b1  = (const float*)d_in[2];
    const float* w2  = (const float*)d_in[3];
    const float* b2  = (const float*)d_in[4];
    const float* w3  = (const float*)d_in[5];
    const float* b3  = (const float*)d_in[6];
    float* out = (float*)d_out;
    prep_kernel<<<2049, 256>>>(in, w1, w2, w3);
    main_kernel<<<NBLK, 256>>>(in, b1, b2, b3);
    final_kernel<<<2048, 256>>>(in, out);
}